// round 1
// baseline (speedup 1.0000x reference)
#include <cuda_runtime.h>
#include <math.h>

#define K_DIM 768
#define N_DIM 3072

// Scratch for masked weight (allocation-free rule: __device__ global)
__device__ float g_wm[N_DIM * K_DIM];

// ---------------------------------------------------------------------------
// Kernel 1: 2:4 mask. One thread per group of 4 weights.
// Zero the 2 smallest-|w| entries (stable: lowest index wins ties),
// matching jax.lax.top_k(-|w|, k=2) semantics in the reference.
// ---------------------------------------------------------------------------
__global__ void mask24_kernel(const float* __restrict__ w,
                              float* __restrict__ wm, int ngroups) {
    int g = blockIdx.x * blockDim.x + threadIdx.x;
    if (g >= ngroups) return;
    float4 v4 = reinterpret_cast<const float4*>(w)[g];
    float v[4] = {v4.x, v4.y, v4.z, v4.w};
    float a[4] = {fabsf(v[0]), fabsf(v[1]), fabsf(v[2]), fabsf(v[3])};

    int i1 = 0;
#pragma unroll
    for (int i = 1; i < 4; i++)
        if (a[i] < a[i1]) i1 = i;            // strict < : earliest index on tie
    int i2 = (i1 == 0) ? 1 : 0;
#pragma unroll
    for (int i = 0; i < 4; i++)
        if (i != i1 && a[i] < a[i2]) i2 = i; // ascending scan, strict < : stable

    v[i1] = 0.0f;
    v[i2] = 0.0f;
    reinterpret_cast<float4*>(wm)[g] = make_float4(v[0], v[1], v[2], v[3]);
}

// ---------------------------------------------------------------------------
// Kernel 2: C[M,N] = A[M,K] * B[N,K]^T + bias[N]   (NT SGEMM, fused bias)
// BM=BN=128, BK=16, 256 threads, 8x8 per-thread microtile,
// register-staged double buffering (one __syncthreads per K-step).
// ---------------------------------------------------------------------------
#define BM 128
#define BN 128
#define BKK 16
#define SPAD 4

__global__ __launch_bounds__(256, 2)
void sgemm_nt_bias(const float* __restrict__ A,   // [M, K]
                   const float* __restrict__ B,   // [N, K] (masked weight)
                   const float* __restrict__ bias,// [N]
                   float* __restrict__ C,         // [M, N]
                   int M) {
    __shared__ float As[2][BKK][BM + SPAD];
    __shared__ float Bs[2][BKK][BN + SPAD];

    const int tid = threadIdx.x;
    const int bm = blockIdx.y * BM;
    const int bn = blockIdx.x * BN;
    const int tx = tid & 15;   // N direction (16)
    const int ty = tid >> 4;   // M direction (16)

    // Global-load mapping: each thread loads 2 float4 from A and 2 from B
    const int lr = tid >> 2;          // 0..63  (tile row)
    const int lc = (tid & 3) << 2;    // 0,4,8,12 (tile k-col)

    float acc[8][8];
#pragma unroll
    for (int i = 0; i < 8; i++)
#pragma unroll
        for (int j = 0; j < 8; j++) acc[i][j] = 0.0f;

    float4 ra[2], rb[2];

    // ---- prologue: load tile 0 ----
#pragma unroll
    for (int h = 0; h < 2; h++) {
        int r = lr + h * 64;
        int gr = bm + r;
        ra[h] = (gr < M)
            ? *reinterpret_cast<const float4*>(A + (size_t)gr * K_DIM + lc)
            : make_float4(0.f, 0.f, 0.f, 0.f);
        rb[h] = *reinterpret_cast<const float4*>(B + (size_t)(bn + r) * K_DIM + lc);
    }
    int buf = 0;
#pragma unroll
    for (int h = 0; h < 2; h++) {
        int r = lr + h * 64;
        As[buf][lc + 0][r] = ra[h].x; As[buf][lc + 1][r] = ra[h].y;
        As[buf][lc + 2][r] = ra[h].z; As[buf][lc + 3][r] = ra[h].w;
        Bs[buf][lc + 0][r] = rb[h].x; Bs[buf][lc + 1][r] = rb[h].y;
        Bs[buf][lc + 2][r] = rb[h].z; Bs[buf][lc + 3][r] = rb[h].w;
    }
    __syncthreads();

    const int NSTEP = K_DIM / BKK;  // 48
    for (int t = 1; t < NSTEP; t++) {
        const int kk = t * BKK;
        // stage next tile's globals into registers
#pragma unroll
        for (int h = 0; h < 2; h++) {
            int r = lr + h * 64;
            int gr = bm + r;
            ra[h] = (gr < M)
                ? *reinterpret_cast<const float4*>(A + (size_t)gr * K_DIM + kk + lc)
                : make_float4(0.f, 0.f, 0.f, 0.f);
            rb[h] = *reinterpret_cast<const float4*>(B + (size_t)(bn + r) * K_DIM + kk + lc);
        }
        // compute current tile
#pragma unroll
        for (int k = 0; k < BKK; k++) {
            float af[8], bf[8];
#pragma unroll
            for (int i = 0; i < 8; i++) af[i] = As[buf][k][ty * 8 + i];
#pragma unroll
            for (int j = 0; j < 8; j++) bf[j] = Bs[buf][k][tx * 8 + j];
#pragma unroll
            for (int i = 0; i < 8; i++)
#pragma unroll
                for (int j = 0; j < 8; j++)
                    acc[i][j] = fmaf(af[i], bf[j], acc[i][j]);
        }
        // store staged registers to the other buffer
        const int nb = buf ^ 1;
#pragma unroll
        for (int h = 0; h < 2; h++) {
            int r = lr + h * 64;
            As[nb][lc + 0][r] = ra[h].x; As[nb][lc + 1][r] = ra[h].y;
            As[nb][lc + 2][r] = ra[h].z; As[nb][lc + 3][r] = ra[h].w;
            Bs[nb][lc + 0][r] = rb[h].x; Bs[nb][lc + 1][r] = rb[h].y;
            Bs[nb][lc + 2][r] = rb[h].z; Bs[nb][lc + 3][r] = rb[h].w;
        }
        __syncthreads();
        buf = nb;
    }
    // final tile compute
#pragma unroll
    for (int k = 0; k < BKK; k++) {
        float af[8], bf[8];
#pragma unroll
        for (int i = 0; i < 8; i++) af[i] = As[buf][k][ty * 8 + i];
#pragma unroll
        for (int j = 0; j < 8; j++) bf[j] = Bs[buf][k][tx * 8 + j];
#pragma unroll
        for (int i = 0; i < 8; i++)
#pragma unroll
            for (int j = 0; j < 8; j++)
                acc[i][j] = fmaf(af[i], bf[j], acc[i][j]);
    }

    // ---- epilogue: add bias, store (vectorized, M-guarded) ----
    const float4 bv0 = *reinterpret_cast<const float4*>(bias + bn + tx * 8);
    const float4 bv1 = *reinterpret_cast<const float4*>(bias + bn + tx * 8 + 4);
#pragma unroll
    for (int i = 0; i < 8; i++) {
        int gr = bm + ty * 8 + i;
        if (gr < M) {
            float4 o0, o1;
            o0.x = acc[i][0] + bv0.x; o0.y = acc[i][1] + bv0.y;
            o0.z = acc[i][2] + bv0.z; o0.w = acc[i][3] + bv0.w;
            o1.x = acc[i][4] + bv1.x; o1.y = acc[i][5] + bv1.y;
            o1.z = acc[i][6] + bv1.z; o1.w = acc[i][7] + bv1.w;
            float* cp = C + (size_t)gr * N_DIM + bn + tx * 8;
            *reinterpret_cast<float4*>(cp)     = o0;
            *reinterpret_cast<float4*>(cp + 4) = o1;
        }
    }
}

// ---------------------------------------------------------------------------
extern "C" void kernel_launch(void* const* d_in, const int* in_sizes, int n_in,
                              void* d_out, int out_size) {
    const float* x    = (const float*)d_in[0];  // [B*S, 768] = [12608, 768]
    const float* w    = (const float*)d_in[1];  // [3072, 768]
    const float* bias = (const float*)d_in[2];  // [3072]
    float* out        = (float*)d_out;          // [B*S, 3072]
    (void)n_in; (void)out_size;

    const int M = in_sizes[0] / K_DIM;          // 12608

    float* wm = nullptr;
    cudaGetSymbolAddress((void**)&wm, g_wm);

    // 1) build masked weight
    const int ngroups = (N_DIM * K_DIM) / 4;    // 589824
    mask24_kernel<<<(ngroups + 255) / 256, 256>>>(w, wm, ngroups);

    // 2) fused SGEMM + bias
    dim3 grid(N_DIM / BN, (M + BM - 1) / BM);   // (24, 99)
    sgemm_nt_bias<<<grid, 256>>>(x, wm, bias, out, M);
}

// round 3
// speedup vs baseline: 2.9851x; 2.9851x over previous
#include <cuda_runtime.h>
#include <cuda_bf16.h>
#include <cstdint>
#include <math.h>

#define K_DIM 768
#define N_DIM 3072
#define M_MAX 12608

#if defined(__CUDA_ARCH__) && defined(__CUDA_ARCH_FEAT_SM103_ALL)
#define USE_TC 1
#else
#define USE_TC 0
#endif

// ---------------- device scratch (allocation-free rule) ----------------
__device__ __nv_bfloat16 g_a_hi[M_MAX * K_DIM];
__device__ __nv_bfloat16 g_a_lo[M_MAX * K_DIM];
__device__ __nv_bfloat16 g_b_hi[N_DIM * K_DIM];
__device__ __nv_bfloat16 g_b_lo[N_DIM * K_DIM];

// ---------------- common PTX helpers (base-target safe) ----------------
__device__ __forceinline__ uint32_t smem_u32(const void* p) {
    uint32_t a;
    asm("{ .reg .u64 t; cvta.to.shared.u64 t, %1; cvt.u32.u64 %0, t; }" : "=r"(a) : "l"(p));
    return a;
}
__device__ __forceinline__ void cpasync16(uint32_t dst, const void* src) {
    asm volatile("cp.async.cg.shared.global [%0], [%1], 16;" :: "r"(dst), "l"(src));
}
#define CP_COMMIT() asm volatile("cp.async.commit_group;" ::: "memory")
__device__ __forceinline__ uint32_t lds32(uint32_t addr) {
    uint32_t v;
    asm volatile("ld.shared.b32 %0, [%1];" : "=r"(v) : "r"(addr));
    return v;
}
__device__ __forceinline__ void mma_bf16(float* c, const uint32_t* a, const uint32_t* b) {
    asm volatile(
        "mma.sync.aligned.m16n8k16.row.col.f32.bf16.bf16.f32 "
        "{%0,%1,%2,%3}, {%4,%5,%6,%7}, {%8,%9}, {%0,%1,%2,%3};"
        : "+f"(c[0]), "+f"(c[1]), "+f"(c[2]), "+f"(c[3])
        : "r"(a[0]), "r"(a[1]), "r"(a[2]), "r"(a[3]), "r"(b[0]), "r"(b[1]));
}

// ---------------- tcgen05 helpers (sm_103a-only pass) ----------------
#if USE_TC
#define MBAR_INIT(addr, cnt) \
    asm volatile("mbarrier.init.shared.b64 [%0], %1;" :: "r"(addr), "r"(cnt) : "memory")
#define MBAR_WAIT(addr, phase) do {                                              \
    asm volatile(                                                                \
        "{\n\t.reg .pred P;\n\t"                                                 \
        "WL_%=:\n\t"                                                             \
        "mbarrier.try_wait.parity.acquire.cta.shared::cta.b64 P, [%0], %1, 0x989680;\n\t" \
        "@P bra.uni WD_%=;\n\t"                                                  \
        "bra.uni WL_%=;\n\t"                                                     \
        "WD_%=:\n\t}"                                                            \
        :: "r"(addr), "r"(phase) : "memory");                                    \
} while (0)
#define TC_ALLOC(smem_dst, ncols) \
    asm volatile("tcgen05.alloc.cta_group::1.sync.aligned.shared::cta.b32 [%0], %1;" \
                 :: "r"(smem_dst), "r"(ncols) : "memory")
#define TC_DEALLOC(tmem, ncols) \
    asm volatile("tcgen05.dealloc.cta_group::1.sync.aligned.b32 %0, %1;" :: "r"(tmem), "r"(ncols))
#define TC_COMMIT(mbar) \
    asm volatile("tcgen05.commit.cta_group::1.mbarrier::arrive::one.shared::cluster.b64 [%0];" \
                 :: "r"(mbar) : "memory")
#define TC_FENCE_AFTER()  asm volatile("tcgen05.fence::after_thread_sync;" ::: "memory")
#define TC_FENCE_BEFORE() asm volatile("tcgen05.fence::before_thread_sync;" ::: "memory")
#define TC_WAIT_LD()      asm volatile("tcgen05.wait::ld.sync.aligned;" ::: "memory")

__device__ __forceinline__ void mma_f16_ss(uint32_t d, uint64_t ad, uint64_t bd,
                                           uint32_t idesc, bool acc) {
    uint32_t en = acc ? 1u : 0u;
    asm volatile(
        "{\n\t.reg .pred p;\n\tsetp.ne.u32 p, %4, 0;\n\t"
        "tcgen05.mma.cta_group::1.kind::f16 [%0], %1, %2, %3, {%5, %5, %5, %5}, p;\n\t}"
        :: "r"(d), "l"(ad), "l"(bd), "r"(idesc), "r"(en), "r"(0u) : "memory");
}
#define TC_LD_X32(r, addr)                                                      \
    asm volatile("tcgen05.ld.sync.aligned.32x32b.x32.b32 "                      \
        "{%0,%1,%2,%3,%4,%5,%6,%7,%8,%9,%10,%11,%12,%13,%14,%15,"               \
        "%16,%17,%18,%19,%20,%21,%22,%23,%24,%25,%26,%27,%28,%29,%30,%31}, [%32];" \
        : "=r"((r)[0]),"=r"((r)[1]),"=r"((r)[2]),"=r"((r)[3]),                   \
          "=r"((r)[4]),"=r"((r)[5]),"=r"((r)[6]),"=r"((r)[7]),                   \
          "=r"((r)[8]),"=r"((r)[9]),"=r"((r)[10]),"=r"((r)[11]),                 \
          "=r"((r)[12]),"=r"((r)[13]),"=r"((r)[14]),"=r"((r)[15]),               \
          "=r"((r)[16]),"=r"((r)[17]),"=r"((r)[18]),"=r"((r)[19]),               \
          "=r"((r)[20]),"=r"((r)[21]),"=r"((r)[22]),"=r"((r)[23]),               \
          "=r"((r)[24]),"=r"((r)[25]),"=r"((r)[26]),"=r"((r)[27]),               \
          "=r"((r)[28]),"=r"((r)[29]),"=r"((r)[30]),"=r"((r)[31]) : "r"(addr))

static constexpr uint64_t DESC_BASE_SW128 =
    (uint64_t(2) << 61) | (uint64_t(1) << 46) | (uint64_t(64) << 32) | (uint64_t(1) << 16);
__device__ __forceinline__ uint64_t make_desc(uint32_t base) {
    return DESC_BASE_SW128 | ((uint64_t)(base >> 4) & 0x3FFF);
}
__device__ __forceinline__ uint32_t swz128(uint32_t o) { return o ^ ((o >> 3) & 0x70); }
#endif  // USE_TC

// ---------------- kernel 1: 2:4 mask + hi/lo split of weight ----------------
__global__ void mask_split_w(const float* __restrict__ w,
                             __nv_bfloat16* __restrict__ bhi,
                             __nv_bfloat16* __restrict__ blo, int ngroups) {
    int g = blockIdx.x * blockDim.x + threadIdx.x;
    if (g >= ngroups) return;
    float4 v4 = reinterpret_cast<const float4*>(w)[g];
    float v[4] = {v4.x, v4.y, v4.z, v4.w};
    float a[4] = {fabsf(v[0]), fabsf(v[1]), fabsf(v[2]), fabsf(v[3])};
    int i1 = 0;
#pragma unroll
    for (int i = 1; i < 4; i++) if (a[i] < a[i1]) i1 = i;      // stable: strict <
    int i2 = (i1 == 0) ? 1 : 0;
#pragma unroll
    for (int i = 0; i < 4; i++)
        if (i != i1 && a[i] < a[i2]) i2 = i;
    v[i1] = 0.0f; v[i2] = 0.0f;
    __nv_bfloat16 h[4], l[4];
#pragma unroll
    for (int i = 0; i < 4; i++) {
        h[i] = __float2bfloat16_rn(v[i]);
        l[i] = __float2bfloat16_rn(v[i] - __bfloat162float(h[i]));
    }
    reinterpret_cast<__nv_bfloat162*>(bhi)[2 * g]     = __nv_bfloat162(h[0], h[1]);
    reinterpret_cast<__nv_bfloat162*>(bhi)[2 * g + 1] = __nv_bfloat162(h[2], h[3]);
    reinterpret_cast<__nv_bfloat162*>(blo)[2 * g]     = __nv_bfloat162(l[0], l[1]);
    reinterpret_cast<__nv_bfloat162*>(blo)[2 * g + 1] = __nv_bfloat162(l[2], l[3]);
}

// ---------------- kernel 2: hi/lo split of x ----------------
__global__ void split_x(const float* __restrict__ x,
                        __nv_bfloat16* __restrict__ ahi,
                        __nv_bfloat16* __restrict__ alo, int nquads) {
    int g = blockIdx.x * blockDim.x + threadIdx.x;
    if (g >= nquads) return;
    float4 v4 = reinterpret_cast<const float4*>(x)[g];
    float v[4] = {v4.x, v4.y, v4.z, v4.w};
    __nv_bfloat16 h[4], l[4];
#pragma unroll
    for (int i = 0; i < 4; i++) {
        h[i] = __float2bfloat16_rn(v[i]);
        l[i] = __float2bfloat16_rn(v[i] - __bfloat162float(h[i]));
    }
    reinterpret_cast<__nv_bfloat162*>(ahi)[2 * g]     = __nv_bfloat162(h[0], h[1]);
    reinterpret_cast<__nv_bfloat162*>(ahi)[2 * g + 1] = __nv_bfloat162(h[2], h[3]);
    reinterpret_cast<__nv_bfloat162*>(alo)[2 * g]     = __nv_bfloat162(l[0], l[1]);
    reinterpret_cast<__nv_bfloat162*>(alo)[2 * g + 1] = __nv_bfloat162(l[2], l[3]);
}

// ---------------- GEMM kernel: one launch shape, two arch paths ----------------
// grid (N/128, ceil(M/128)), 256 threads, dyn smem = SMEM_TOTAL.
// Base target: HMMA mma.sync bf16, 3-stage cp.async, BK=32.
// sm_103a pass (if present): tcgen05, 2-stage, BK=64.
#define SMEM_TOTAL 132096

__global__ __launch_bounds__(256, 1)
void gemm_kernel(const __nv_bfloat16* __restrict__ Ahi, const __nv_bfloat16* __restrict__ Alo,
                 const __nv_bfloat16* __restrict__ Bhi, const __nv_bfloat16* __restrict__ Blo,
                 const float* __restrict__ bias, float* __restrict__ C, int M) {
    extern __shared__ char smem[];
    const uint32_t sbase = smem_u32(smem);
    const int tid = threadIdx.x;
    const int bm = blockIdx.y * 128;
    const int bn = blockIdx.x * 128;

#if USE_TC
    // ======================= tcgen05 path =======================
    // layout: [0] tmem ptr, [8)(16) mbar0/1, stages at 1024, stride 65536:
    //   AHI +0 (16K), ALO +16384, BHI +32768, BLO +49152  (128 rows x 128B, SW128)
    const int wid = tid >> 5;
    const int lane = tid & 31;
    const int NCH = K_DIM / 64;  // 12

    if (wid == 0) TC_ALLOC(sbase + 0, 128);
    if (tid == 0) { MBAR_INIT(sbase + 8, 1); MBAR_INIT(sbase + 16, 1); }
    __syncthreads();
    uint32_t tmem;
    asm volatile("ld.shared.b32 %0, [%1];" : "=r"(tmem) : "r"(sbase + 0));

    const uint32_t IDESC_T =
        (1u << 4) | (1u << 7) | (1u << 10) | ((128u / 8) << 17) | ((128u / 16) << 24);

    auto load_chunk = [&](int t, int s) {
        const uint32_t stg = sbase + 1024 + s * 65536;
        const int kk = t * 64;
#pragma unroll
        for (int j = 0; j < 4; j++) {
            int i = tid + 256 * j;         // 0..1023
            int r = i >> 3, c = i & 7;
            uint32_t off = swz128((uint32_t)(r * 128 + c * 16));
            int gr = bm + r; if (gr > M - 1) gr = M - 1;
            const size_t ga = (size_t)gr * K_DIM + kk + c * 8;
            const size_t gb = (size_t)(bn + r) * K_DIM + kk + c * 8;
            cpasync16(stg + 0     + off, Ahi + ga);
            cpasync16(stg + 16384 + off, Alo + ga);
            cpasync16(stg + 32768 + off, Bhi + gb);
            cpasync16(stg + 49152 + off, Blo + gb);
        }
        CP_COMMIT();
    };

    load_chunk(0, 0);
    load_chunk(1, 1);

    int ph[2] = {0, 0};
    for (int t = 0; t < NCH; t++) {
        const int s = t & 1;
        if (t == NCH - 1) asm volatile("cp.async.wait_group 0;" ::: "memory");
        else              asm volatile("cp.async.wait_group 1;" ::: "memory");
        __syncthreads();

        if (tid == 0) {
            asm volatile("fence.proxy.async.shared::cta;" ::: "memory");
            const uint32_t stg = sbase + 1024 + s * 65536;
            const uint64_t dAhi = make_desc(stg + 0);
            const uint64_t dAlo = make_desc(stg + 16384);
            const uint64_t dBhi = make_desc(stg + 32768);
            const uint64_t dBlo = make_desc(stg + 49152);
#pragma unroll
            for (int ks = 0; ks < 4; ks++) {
#pragma unroll
                for (int pass = 0; pass < 3; pass++) {
                    uint64_t ad = (pass == 2) ? dAlo : dAhi;
                    uint64_t bd = (pass == 1) ? dBlo : dBhi;
                    bool acc = !(t == 0 && ks == 0 && pass == 0);
                    mma_f16_ss(tmem, ad + ks * 2, bd + ks * 2, IDESC_T, acc);
                }
            }
            TC_COMMIT(sbase + 8 + s * 8);
        }

        if (t + 2 < NCH) {
            MBAR_WAIT(sbase + 8 + s * 8, ph[s]);
            ph[s] ^= 1;
            load_chunk(t + 2, s);
        }
    }
    MBAR_WAIT(sbase + 8, ph[0]);
    MBAR_WAIT(sbase + 16, ph[1]);
    TC_FENCE_AFTER();

    // epilogue: warp w -> lanes (w&3)*32, col half (w>>2)*64
    {
        const int lg = wid & 3;
        const int h = wid >> 2;
        const int row = bm + lg * 32 + lane;
#pragma unroll
        for (int cb = 0; cb < 2; cb++) {
            uint32_t r[32];
            TC_LD_X32(r, tmem + h * 64 + cb * 32);
            TC_WAIT_LD();
            if (row < M) {
                const int col0 = bn + h * 64 + cb * 32;
                float* cp = C + (size_t)row * N_DIM + col0;
#pragma unroll
                for (int q = 0; q < 8; q++) {
                    float4 o;
                    o.x = __uint_as_float(r[4 * q + 0]) + __ldg(bias + col0 + 4 * q + 0);
                    o.y = __uint_as_float(r[4 * q + 1]) + __ldg(bias + col0 + 4 * q + 1);
                    o.z = __uint_as_float(r[4 * q + 2]) + __ldg(bias + col0 + 4 * q + 2);
                    o.w = __uint_as_float(r[4 * q + 3]) + __ldg(bias + col0 + 4 * q + 3);
                    *reinterpret_cast<float4*>(cp + 4 * q) = o;
                }
            }
        }
    }
    TC_FENCE_BEFORE();
    __syncthreads();
    if (tid == 0) {
        asm volatile("mbarrier.inval.shared.b64 [%0];" :: "r"(sbase + 8) : "memory");
        asm volatile("mbarrier.inval.shared.b64 [%0];" :: "r"(sbase + 16) : "memory");
    }
    if (wid == 0) TC_DEALLOC(tmem, 128);

#else
    // ======================= HMMA path (base target) =======================
    // 3 stages x 32KB: AHI +0, ALO +8192, BHI +16384, BLO +24576
    // tiles: 128 rows x 32 bf16 (64B rows), chunk-XOR swizzle for bank-free access.
    const int wid = tid >> 5;
    const int lane = tid & 31;
    const int wm = wid & 3;        // M warp (32 rows)
    const int wn = wid >> 2;       // N warp (64 cols)
    const int u = lane >> 2;       // 0..7
    const int w = lane & 3;        // 0..3
    const int NCH = K_DIM / 32;    // 24

    auto swf = [](int r, int kc) -> uint32_t {
        int chunk = kc >> 3;
        return (uint32_t)(r * 64 + ((chunk ^ ((r >> 1) & 3)) << 4) + (kc & 7) * 2);
    };

    auto ld_stage = [&](int t, int s) {
        const uint32_t stg = sbase + s * 32768;
        const int kk = t * 32;
#pragma unroll
        for (int j = 0; j < 2; j++) {
            int idx = tid + 256 * j;   // 0..511
            int r = idx >> 2, c = idx & 3;
            uint32_t sw = (uint32_t)(r * 64 + ((c ^ ((r >> 1) & 3)) << 4));
            int gra = bm + r; if (gra > M - 1) gra = M - 1;
            const size_t ga = (size_t)gra * K_DIM + kk + c * 8;
            const size_t gb = (size_t)(bn + r) * K_DIM + kk + c * 8;
            cpasync16(stg + 0     + sw, Ahi + ga);
            cpasync16(stg + 8192  + sw, Alo + ga);
            cpasync16(stg + 16384 + sw, Bhi + gb);
            cpasync16(stg + 24576 + sw, Blo + gb);
        }
        CP_COMMIT();
    };

    float acc[2][8][4];
#pragma unroll
    for (int mt = 0; mt < 2; mt++)
#pragma unroll
        for (int nt = 0; nt < 8; nt++)
#pragma unroll
            for (int q = 0; q < 4; q++) acc[mt][nt][q] = 0.0f;

    ld_stage(0, 0); ld_stage(1, 1); ld_stage(2, 2);

    for (int t = 0; t < NCH; t++) {
        if (t <= NCH - 3)      asm volatile("cp.async.wait_group 2;" ::: "memory");
        else if (t == NCH - 2) asm volatile("cp.async.wait_group 1;" ::: "memory");
        else                   asm volatile("cp.async.wait_group 0;" ::: "memory");
        __syncthreads();

        const uint32_t stg = sbase + (t % 3) * 32768;
#pragma unroll
        for (int ks = 0; ks < 2; ks++) {
            uint32_t fah[2][4], fal[2][4], fbh[8][2], fbl[8][2];
#pragma unroll
            for (int mt = 0; mt < 2; mt++)
#pragma unroll
                for (int rg = 0; rg < 4; rg++) {
                    int r = wm * 32 + mt * 16 + u + ((rg & 1) << 3);
                    int kc = ks * 16 + w * 2 + ((rg >> 1) << 3);
                    uint32_t o = swf(r, kc);
                    fah[mt][rg] = lds32(stg + 0 + o);
                    fal[mt][rg] = lds32(stg + 8192 + o);
                }
#pragma unroll
            for (int nt = 0; nt < 8; nt++)
#pragma unroll
                for (int rg = 0; rg < 2; rg++) {
                    int r = wn * 64 + nt * 8 + u;
                    int kc = ks * 16 + w * 2 + (rg << 3);
                    uint32_t o = swf(r, kc);
                    fbh[nt][rg] = lds32(stg + 16384 + o);
                    fbl[nt][rg] = lds32(stg + 24576 + o);
                }
#pragma unroll
            for (int mt = 0; mt < 2; mt++)
#pragma unroll
                for (int nt = 0; nt < 8; nt++) {
                    mma_bf16(acc[mt][nt], fah[mt], fbh[nt]);   // hi*hi
                    mma_bf16(acc[mt][nt], fah[mt], fbl[nt]);   // hi*lo
                    mma_bf16(acc[mt][nt], fal[mt], fbh[nt]);   // lo*hi
                }
        }
        __syncthreads();
        if (t + 3 < NCH) ld_stage(t + 3, t % 3);
    }

    // epilogue: bias + store (float2 per acc pair)
#pragma unroll
    for (int nt = 0; nt < 8; nt++) {
        const int col = bn + wn * 64 + nt * 8 + w * 2;
        const float b0 = __ldg(bias + col);
        const float b1 = __ldg(bias + col + 1);
#pragma unroll
        for (int mt = 0; mt < 2; mt++) {
            const int r0 = bm + wm * 32 + mt * 16 + u;
            if (r0 < M) {
                float2 v = make_float2(acc[mt][nt][0] + b0, acc[mt][nt][1] + b1);
                *reinterpret_cast<float2*>(C + (size_t)r0 * N_DIM + col) = v;
            }
            const int r1 = r0 + 8;
            if (r1 < M) {
                float2 v = make_float2(acc[mt][nt][2] + b0, acc[mt][nt][3] + b1);
                *reinterpret_cast<float2*>(C + (size_t)r1 * N_DIM + col) = v;
            }
        }
    }
#endif
}

// ---------------------------------------------------------------------------
extern "C" void kernel_launch(void* const* d_in, const int* in_sizes, int n_in,
                              void* d_out, int out_size) {
    const float* x    = (const float*)d_in[0];  // [M, 768]
    const float* w    = (const float*)d_in[1];  // [3072, 768]
    const float* bias = (const float*)d_in[2];  // [3072]
    float* out        = (float*)d_out;
    (void)n_in; (void)out_size;

    const int M = in_sizes[0] / K_DIM;          // 12608

    __nv_bfloat16 *ahi, *alo, *bhi, *blo;
    cudaGetSymbolAddress((void**)&ahi, g_a_hi);
    cudaGetSymbolAddress((void**)&alo, g_a_lo);
    cudaGetSymbolAddress((void**)&bhi, g_b_hi);
    cudaGetSymbolAddress((void**)&blo, g_b_lo);

    const int ngroups = (N_DIM * K_DIM) / 4;
    mask_split_w<<<(ngroups + 255) / 256, 256>>>(w, bhi, blo, ngroups);
    const int nquads = (M * K_DIM) / 4;
    split_x<<<(nquads + 255) / 256, 256>>>(x, ahi, alo, nquads);

    cudaFuncSetAttribute(gemm_kernel, cudaFuncAttributeMaxDynamicSharedMemorySize, SMEM_TOTAL);
    dim3 grid(N_DIM / 128, (M + 127) / 128);    // (24, 99)
    gemm_kernel<<<grid, 256, SMEM_TOTAL>>>(ahi, alo, bhi, blo, bias, out, M);
}

// round 8
// speedup vs baseline: 3.8430x; 1.2874x over previous
#include <cuda_runtime.h>
#include <cuda_bf16.h>
#include <cstdint>
#include <math.h>

#define K_DIM 768
#define N_DIM 3072
#define M_MAX 12608
#define NCHUNK 12            // K / 64

// ---------------- device scratch (allocation-free rule) ----------------
__device__ __nv_bfloat16 g_a_hi[M_MAX * K_DIM];        // x hi  [M, K]
__device__ __nv_bfloat16 g_a_lo[M_MAX * K_DIM];        // x lo  [M, K]
// compressed W: per row, per k64 chunk: [hi h0(16) | hi h1(16) | lo h0(16) | lo h1(16)] bf16
__device__ __nv_bfloat16 g_wc[N_DIM * NCHUNK * 64];
__device__ uint32_t g_meta[N_DIM * 24];                // [row][k32 block], nibble q = group q

// ---------------- PTX helpers (base-target safe) ----------------
__device__ __forceinline__ uint32_t smem_u32(const void* p) {
    uint32_t a;
    asm("{ .reg .u64 t; cvta.to.shared.u64 t, %1; cvt.u32.u64 %0, t; }" : "=r"(a) : "l"(p));
    return a;
}
__device__ __forceinline__ void cpasync16(uint32_t dst, const void* src) {
    asm volatile("cp.async.cg.shared.global [%0], [%1], 16;" :: "r"(dst), "l"(src));
}
__device__ __forceinline__ void cpasync8(uint32_t dst, const void* src) {
    asm volatile("cp.async.ca.shared.global [%0], [%1], 8;" :: "r"(dst), "l"(src));
}
#define CP_COMMIT() asm volatile("cp.async.commit_group;" ::: "memory")
__device__ __forceinline__ uint32_t lds32(uint32_t addr) {
    uint32_t v;
    asm volatile("ld.shared.b32 %0, [%1];" : "=r"(v) : "r"(addr));
    return v;
}
__device__ __forceinline__ void sts32(uint32_t addr, float v) {
    asm volatile("st.shared.f32 [%0], %1;" :: "r"(addr), "f"(v));
}
__device__ __forceinline__ float4 lds128(uint32_t addr) {
    float4 v;
    asm volatile("ld.shared.v4.f32 {%0,%1,%2,%3}, [%4];"
                 : "=f"(v.x), "=f"(v.y), "=f"(v.z), "=f"(v.w) : "r"(addr));
    return v;
}
// sparse MMA: A = m16xk32 2:4 (compressed 4 regs), B = k32xn8 (4 regs), same e all passes
__device__ __forceinline__ void mma_sp_bf16(float* c, const uint32_t* a,
                                            const uint32_t* b, uint32_t e) {
    asm volatile(
        "mma.sp::ordered_metadata.sync.aligned.m16n8k32.row.col.f32.bf16.bf16.f32 "
        "{%0,%1,%2,%3}, {%4,%5,%6,%7}, {%8,%9,%10,%11}, {%0,%1,%2,%3}, %12, 0x0;"
        : "+f"(c[0]), "+f"(c[1]), "+f"(c[2]), "+f"(c[3])
        : "r"(a[0]), "r"(a[1]), "r"(a[2]), "r"(a[3]),
          "r"(b[0]), "r"(b[1]), "r"(b[2]), "r"(b[3]), "r"(e));
}
__device__ __forceinline__ uint32_t pack_bf2(float a, float b) {
    __nv_bfloat162 p(__float2bfloat16_rn(a), __float2bfloat16_rn(b));
    return *reinterpret_cast<uint32_t*>(&p);
}

// ---------------- kernel 1: 2:4 prune + compress + hi/lo split + metadata ----------------
// one thread per (row, k32 block): reads 32 floats, emits 16 hi + 16 lo bf16 + u32 meta
__global__ void mask_compress_w(const float* __restrict__ w,
                                __nv_bfloat16* __restrict__ wc,
                                uint32_t* __restrict__ meta, int total) {
    int idx = blockIdx.x * blockDim.x + threadIdx.x;
    if (idx >= total) return;                   // total = 3072 * 24
    const int row = idx / 24, kb = idx % 24;
    const float4* src = reinterpret_cast<const float4*>(w + (size_t)row * K_DIM + kb * 32);

    uint32_t hw[8], lw[8], m = 0;
#pragma unroll
    for (int gq = 0; gq < 8; gq++) {
        float4 q = src[gq];
        float v[4] = {q.x, q.y, q.z, q.w};
        float a[4] = {fabsf(v[0]), fabsf(v[1]), fabsf(v[2]), fabsf(v[3])};
        int p1 = 0;
#pragma unroll
        for (int i = 1; i < 4; i++) if (a[i] < a[p1]) p1 = i;     // stable: strict <
        int p2 = (p1 == 0) ? 1 : 0;
#pragma unroll
        for (int i = 0; i < 4; i++)
            if (i != p1 && i != p2 && a[i] < a[p2]) p2 = i;
        // kept indices ascending (complement of pruned)
        int j0 = -1, j1 = -1;
#pragma unroll
        for (int i = 0; i < 4; i++)
            if (i != p1 && i != p2) { if (j0 < 0) j0 = i; else j1 = i; }
        m |= (uint32_t)(j0 | (j1 << 2)) << (4 * gq);
        float v0 = v[j0], v1 = v[j1];
        float h0 = __bfloat162float(__float2bfloat16_rn(v0));
        float h1 = __bfloat162float(__float2bfloat16_rn(v1));
        hw[gq] = pack_bf2(v0, v1);
        lw[gq] = pack_bf2(v0 - h0, v1 - h1);
    }
    const int ch = kb >> 1, h = kb & 1;
    __nv_bfloat16* dst = wc + ((size_t)row * NCHUNK + ch) * 64;
    uint4* dhi = reinterpret_cast<uint4*>(dst + h * 16);        // 32B aligned
    uint4* dlo = reinterpret_cast<uint4*>(dst + 32 + h * 16);
    dhi[0] = make_uint4(hw[0], hw[1], hw[2], hw[3]);
    dhi[1] = make_uint4(hw[4], hw[5], hw[6], hw[7]);
    dlo[0] = make_uint4(lw[0], lw[1], lw[2], lw[3]);
    dlo[1] = make_uint4(lw[4], lw[5], lw[6], lw[7]);
    meta[(size_t)row * 24 + kb] = m;
}

// ---------------- kernel 2: hi/lo split of x ----------------
__global__ void split_x(const float* __restrict__ x,
                        __nv_bfloat16* __restrict__ ahi,
                        __nv_bfloat16* __restrict__ alo, int nquads) {
    int g = blockIdx.x * blockDim.x + threadIdx.x;
    if (g >= nquads) return;
    float4 v4 = reinterpret_cast<const float4*>(x)[g];
    float v[4] = {v4.x, v4.y, v4.z, v4.w};
    uint32_t h0 = pack_bf2(v[0], v[1]), h1 = pack_bf2(v[2], v[3]);
    float f0 = __bfloat162float(__float2bfloat16_rn(v[0]));
    float f1 = __bfloat162float(__float2bfloat16_rn(v[1]));
    float f2 = __bfloat162float(__float2bfloat16_rn(v[2]));
    float f3 = __bfloat162float(__float2bfloat16_rn(v[3]));
    uint32_t l0 = pack_bf2(v[0] - f0, v[1] - f1), l1 = pack_bf2(v[2] - f2, v[3] - f3);
    reinterpret_cast<uint2*>(ahi)[g] = make_uint2(h0, h1);
    reinterpret_cast<uint2*>(alo)[g] = make_uint2(l0, l1);
}

// ---------------- kernel 3: sparse GEMM  CT[N, M] = W(2:4) * XT, transposed store ----------------
// CTA: 128 features x 128 tokens, k64 chunks, 2-stage cp.async, occ 2.
// stage: A(wc) 16K @0, Bhi 16K @16384, Blo 16K @32768, meta 1K @49152
#define ST_A   0
#define ST_BH  16384
#define ST_BL  32768
#define ST_ME  49152
#define ST_SZ  50176
#define SMEM_TOTAL (2 * ST_SZ)   // 100352
#define EPI_STRIDE 36            // floats per token row (144B: 16B-aligned for lds128)

__global__ __launch_bounds__(256, 2)
void gemm_sp(const __nv_bfloat16* __restrict__ Wc, const uint32_t* __restrict__ Meta,
             const __nv_bfloat16* __restrict__ Xhi, const __nv_bfloat16* __restrict__ Xlo,
             const float* __restrict__ bias, float* __restrict__ C, int M) {
    extern __shared__ char smem[];
    const uint32_t sbase = smem_u32(smem);
    const int tid = threadIdx.x;
    const int wid = tid >> 5, lane = tid & 31;
    const int g = lane >> 2, t4 = lane & 3;
    const int kh = lane & 1;           // meta k-half this thread supplies (CUTLASS-derived layout)
    const int wr = wid & 3;            // feature warp: 32 features
    const int wt = wid >> 2;           // token warp: 64 tokens
    const int bn = blockIdx.x * 128;   // feature tile
    const int bt = blockIdx.y * 128;   // token tile

    auto ld_stage = [&](int t, int s) {
        const uint32_t stg = sbase + s * ST_SZ;
#pragma unroll
        for (int j = 0; j < 4; j++) {
            int i = tid + 256 * j;          // 0..1023
            int r = i >> 3, c = i & 7;
            uint32_t sw = (uint32_t)(r * 128 + (((c) ^ (r & 7)) << 4));
            // A: compressed W rows (always valid)
            cpasync16(stg + ST_A + sw, Wc + ((size_t)(bn + r) * NCHUNK + t) * 64 + c * 8);
            // B: token rows (clamped)
            int tok = bt + r; if (tok > M - 1) tok = M - 1;
            const size_t go = (size_t)tok * K_DIM + t * 64 + c * 8;
            cpasync16(stg + ST_BH + sw, Xhi + go);
            cpasync16(stg + ST_BL + sw, Xlo + go);
        }
        if (tid < 128)
            cpasync8(stg + ST_ME + tid * 8, Meta + (size_t)(bn + tid) * 24 + t * 2);
        CP_COMMIT();
    };

    float acc[2][8][4];
#pragma unroll
    for (int mt = 0; mt < 2; mt++)
#pragma unroll
        for (int nt = 0; nt < 8; nt++)
#pragma unroll
            for (int q = 0; q < 4; q++) acc[mt][nt][q] = 0.0f;

    ld_stage(0, 0);
    ld_stage(1, 1);

    for (int t = 0; t < NCHUNK; t++) {
        if (t == NCHUNK - 1) asm volatile("cp.async.wait_group 0;" ::: "memory");
        else                 asm volatile("cp.async.wait_group 1;" ::: "memory");
        __syncthreads();

        const uint32_t stg = sbase + (t & 1) * ST_SZ;
#pragma unroll
        for (int h = 0; h < 2; h++) {                 // two k32 steps per chunk
            uint32_t e[2], ah[2][4], al[2][4];
#pragma unroll
            for (int mt = 0; mt < 2; mt++) {
                const int rbase = wr * 32 + mt * 16;
                const int r0 = rbase + g;             // rows for a0/a2
                const int r1 = r0 + 8;                // rows for a1/a3
                // metadata (m16n8k32, selector 0): thread pair {T_even, T_odd} of each quad.
                //   T_even: k0..15 of rows g (low 16b) and g+8 (high 16b)
                //   T_odd : k16..31 of rows g and g+8
                const uint32_t m_a = lds32(stg + ST_ME + r0 * 8 + h * 4);
                const uint32_t m_b = lds32(stg + ST_ME + r1 * 8 + h * 4);
                e[mt] = ((m_a >> (16 * kh)) & 0xFFFFu) | (((m_b >> (16 * kh)) & 0xFFFFu) << 16);
                const uint32_t b0 = stg + ST_A + r0 * 128;
                const uint32_t b1 = stg + ST_A + r1 * 128;
                ah[mt][0] = lds32(b0 + (((h * 2    ) ^ (r0 & 7)) << 4) + 4 * t4);
                ah[mt][1] = lds32(b1 + (((h * 2    ) ^ (r1 & 7)) << 4) + 4 * t4);
                ah[mt][2] = lds32(b0 + (((h * 2 + 1) ^ (r0 & 7)) << 4) + 4 * t4);
                ah[mt][3] = lds32(b1 + (((h * 2 + 1) ^ (r1 & 7)) << 4) + 4 * t4);
                al[mt][0] = lds32(b0 + (((h * 2 + 4) ^ (r0 & 7)) << 4) + 4 * t4);
                al[mt][1] = lds32(b1 + (((h * 2 + 4) ^ (r1 & 7)) << 4) + 4 * t4);
                al[mt][2] = lds32(b0 + (((h * 2 + 5) ^ (r0 & 7)) << 4) + 4 * t4);
                al[mt][3] = lds32(b1 + (((h * 2 + 5) ^ (r1 & 7)) << 4) + 4 * t4);
            }
#pragma unroll
            for (int nt = 0; nt < 8; nt++) {
                const int tok = wt * 64 + nt * 8 + g;
                const uint32_t bb = tok * 128 + 4 * t4;
                uint32_t bh[4], bl[4];
#pragma unroll
                for (int j = 0; j < 4; j++) {
                    const uint32_t sw = (((4 * h + j) ^ (tok & 7)) << 4);
                    bh[j] = lds32(stg + ST_BH + bb + sw);
                    bl[j] = lds32(stg + ST_BL + bb + sw);
                }
#pragma unroll
                for (int mt = 0; mt < 2; mt++) {
                    mma_sp_bf16(acc[mt][nt], ah[mt], bh, e[mt]);   // hi*hi
                    mma_sp_bf16(acc[mt][nt], ah[mt], bl, e[mt]);   // hi*lo
                    mma_sp_bf16(acc[mt][nt], al[mt], bh, e[mt]);   // lo*hi
                }
            }
        }
        __syncthreads();
        if (t + 2 < NCHUNK) ld_stage(t + 2, t & 1);
    }

    // ---- epilogue: bias + smem transpose (CT frag -> C[token][feature]) ----
    __syncthreads();   // done reading stages; reuse smem
    float bias_v[2][2];
#pragma unroll
    for (int mt = 0; mt < 2; mt++) {
        const int f = bn + wr * 32 + mt * 16 + g;
        bias_v[mt][0] = __ldg(bias + f);
        bias_v[mt][1] = __ldg(bias + f + 8);
    }
    // warp-private region: 64 tokens x EPI_STRIDE floats (144B rows: aligned + near-conflict-free)
    const uint32_t wb = sbase + wid * (64 * EPI_STRIDE * 4);
#pragma unroll
    for (int mt = 0; mt < 2; mt++)
#pragma unroll
        for (int nt = 0; nt < 8; nt++) {
            const int tokL = nt * 8 + 2 * t4;
            const int fL = mt * 16 + g;
            const uint32_t a0 = wb + (uint32_t)(tokL * EPI_STRIDE + fL) * 4;
            sts32(a0,                        acc[mt][nt][0] + bias_v[mt][0]);
            sts32(a0 + EPI_STRIDE * 4,       acc[mt][nt][1] + bias_v[mt][0]);  // token+1
            sts32(a0 + 32,                   acc[mt][nt][2] + bias_v[mt][1]);  // feat+8
            sts32(a0 + EPI_STRIDE * 4 + 32,  acc[mt][nt][3] + bias_v[mt][1]);
        }
    __syncwarp();
#pragma unroll
    for (int it = 0; it < 8; it++) {
        const int tokL = it * 8 + g;
        const int tokG = bt + wt * 64 + tokL;
        if (tokG < M) {
#pragma unroll
            for (int j = 0; j < 2; j++) {
                const int fl = t4 * 4 + j * 16;
                float4 v = lds128(wb + (uint32_t)(tokL * EPI_STRIDE + fl) * 4);
                *reinterpret_cast<float4*>(C + (size_t)tokG * N_DIM + bn + wr * 32 + fl) = v;
            }
        }
    }
}

// ---------------------------------------------------------------------------
extern "C" void kernel_launch(void* const* d_in, const int* in_sizes, int n_in,
                              void* d_out, int out_size) {
    const float* x    = (const float*)d_in[0];  // [M, 768]
    const float* w    = (const float*)d_in[1];  // [3072, 768]
    const float* bias = (const float*)d_in[2];  // [3072]
    float* out        = (float*)d_out;          // [M, 3072]
    (void)n_in; (void)out_size;

    const int M = in_sizes[0] / K_DIM;          // 12608

    __nv_bfloat16 *ahi, *alo, *wc;
    uint32_t* meta;
    cudaGetSymbolAddress((void**)&ahi, g_a_hi);
    cudaGetSymbolAddress((void**)&alo, g_a_lo);
    cudaGetSymbolAddress((void**)&wc, g_wc);
    cudaGetSymbolAddress((void**)&meta, g_meta);

    const int totalW = N_DIM * 24;              // (row, k32 block)
    mask_compress_w<<<(totalW + 255) / 256, 256>>>(w, wc, meta, totalW);
    const int nquads = (M * K_DIM) / 4;
    split_x<<<(nquads + 255) / 256, 256>>>(x, ahi, alo, nquads);

    cudaFuncSetAttribute(gemm_sp, cudaFuncAttributeMaxDynamicSharedMemorySize, SMEM_TOTAL);
    dim3 grid(N_DIM / 128, (M + 127) / 128);    // (24, 99)
    gemm_sp<<<grid, 256, SMEM_TOTAL>>>(wc, meta, ahi, alo, bias, out, M);
}

// round 10
// speedup vs baseline: 4.2237x; 1.0991x over previous
#include <cuda_runtime.h>
#include <cuda_bf16.h>
#include <cstdint>
#include <math.h>

#define K_DIM 768
#define N_DIM 3072
#define M_MAX 12608
#define NCHUNK 12            // K / 64

// ---------------- device scratch (allocation-free rule) ----------------
__device__ __nv_bfloat16 g_a_hi[M_MAX * K_DIM];        // x hi  [M, K]
__device__ __nv_bfloat16 g_a_lo[M_MAX * K_DIM];        // x lo  [M, K]
// compressed W: per row, per k64 chunk: [hi h0(16) | hi h1(16) | lo h0(16) | lo h1(16)] bf16
__device__ __nv_bfloat16 g_wc[N_DIM * NCHUNK * 64];
__device__ uint32_t g_meta[N_DIM * 24];                // [row][k32 block], nibble q = group q

// ---------------- PTX helpers (base-target safe) ----------------
__device__ __forceinline__ uint32_t smem_u32(const void* p) {
    uint32_t a;
    asm("{ .reg .u64 t; cvta.to.shared.u64 t, %1; cvt.u32.u64 %0, t; }" : "=r"(a) : "l"(p));
    return a;
}
__device__ __forceinline__ void cpasync16(uint32_t dst, const void* src) {
    asm volatile("cp.async.cg.shared.global [%0], [%1], 16;" :: "r"(dst), "l"(src));
}
__device__ __forceinline__ void cpasync8(uint32_t dst, const void* src) {
    asm volatile("cp.async.ca.shared.global [%0], [%1], 8;" :: "r"(dst), "l"(src));
}
#define CP_COMMIT() asm volatile("cp.async.commit_group;" ::: "memory")
__device__ __forceinline__ uint32_t lds32(uint32_t addr) {
    uint32_t v;
    asm volatile("ld.shared.b32 %0, [%1];" : "=r"(v) : "r"(addr));
    return v;
}
__device__ __forceinline__ void sts32(uint32_t addr, float v) {
    asm volatile("st.shared.f32 [%0], %1;" :: "r"(addr), "f"(v));
}
__device__ __forceinline__ float4 lds128(uint32_t addr) {
    float4 v;
    asm volatile("ld.shared.v4.f32 {%0,%1,%2,%3}, [%4];"
                 : "=f"(v.x), "=f"(v.y), "=f"(v.z), "=f"(v.w) : "r"(addr));
    return v;
}
__device__ __forceinline__ void ldsm4(uint32_t* r, uint32_t addr) {
    asm volatile("ldmatrix.sync.aligned.m8n8.x4.shared.b16 {%0,%1,%2,%3}, [%4];"
                 : "=r"(r[0]), "=r"(r[1]), "=r"(r[2]), "=r"(r[3]) : "r"(addr));
}
// sparse MMA: A = m16xk32 2:4 (compressed 4 regs), B = k32xn8 (4 regs), same e all passes
__device__ __forceinline__ void mma_sp_bf16(float* c, const uint32_t* a,
                                            const uint32_t* b, uint32_t e) {
    asm volatile(
        "mma.sp::ordered_metadata.sync.aligned.m16n8k32.row.col.f32.bf16.bf16.f32 "
        "{%0,%1,%2,%3}, {%4,%5,%6,%7}, {%8,%9,%10,%11}, {%0,%1,%2,%3}, %12, 0x0;"
        : "+f"(c[0]), "+f"(c[1]), "+f"(c[2]), "+f"(c[3])
        : "r"(a[0]), "r"(a[1]), "r"(a[2]), "r"(a[3]),
          "r"(b[0]), "r"(b[1]), "r"(b[2]), "r"(b[3]), "r"(e));
}
__device__ __forceinline__ uint32_t pack_bf2(float a, float b) {
    __nv_bfloat162 p(__float2bfloat16_rn(a), __float2bfloat16_rn(b));
    return *reinterpret_cast<uint32_t*>(&p);
}

// ---------------- kernel 1: 2:4 prune + compress + hi/lo split + metadata ----------------
__global__ void mask_compress_w(const float* __restrict__ w,
                                __nv_bfloat16* __restrict__ wc,
                                uint32_t* __restrict__ meta, int total) {
    int idx = blockIdx.x * blockDim.x + threadIdx.x;
    if (idx >= total) return;                   // total = 3072 * 24
    const int row = idx / 24, kb = idx % 24;
    const float4* src = reinterpret_cast<const float4*>(w + (size_t)row * K_DIM + kb * 32);

    uint32_t hw[8], lw[8], m = 0;
#pragma unroll
    for (int gq = 0; gq < 8; gq++) {
        float4 q = src[gq];
        float v[4] = {q.x, q.y, q.z, q.w};
        float a[4] = {fabsf(v[0]), fabsf(v[1]), fabsf(v[2]), fabsf(v[3])};
        int p1 = 0;
#pragma unroll
        for (int i = 1; i < 4; i++) if (a[i] < a[p1]) p1 = i;     // stable: strict <
        int p2 = (p1 == 0) ? 1 : 0;
#pragma unroll
        for (int i = 0; i < 4; i++)
            if (i != p1 && i != p2 && a[i] < a[p2]) p2 = i;
        int j0 = -1, j1 = -1;
#pragma unroll
        for (int i = 0; i < 4; i++)
            if (i != p1 && i != p2) { if (j0 < 0) j0 = i; else j1 = i; }
        m |= (uint32_t)(j0 | (j1 << 2)) << (4 * gq);
        float v0 = v[j0], v1 = v[j1];
        float h0 = __bfloat162float(__float2bfloat16_rn(v0));
        float h1 = __bfloat162float(__float2bfloat16_rn(v1));
        hw[gq] = pack_bf2(v0, v1);
        lw[gq] = pack_bf2(v0 - h0, v1 - h1);
    }
    const int ch = kb >> 1, h = kb & 1;
    __nv_bfloat16* dst = wc + ((size_t)row * NCHUNK + ch) * 64;
    uint4* dhi = reinterpret_cast<uint4*>(dst + h * 16);
    uint4* dlo = reinterpret_cast<uint4*>(dst + 32 + h * 16);
    dhi[0] = make_uint4(hw[0], hw[1], hw[2], hw[3]);
    dhi[1] = make_uint4(hw[4], hw[5], hw[6], hw[7]);
    dlo[0] = make_uint4(lw[0], lw[1], lw[2], lw[3]);
    dlo[1] = make_uint4(lw[4], lw[5], lw[6], lw[7]);
    meta[(size_t)row * 24 + kb] = m;
}

// ---------------- kernel 2: hi/lo split of x ----------------
__global__ void split_x(const float* __restrict__ x,
                        __nv_bfloat16* __restrict__ ahi,
                        __nv_bfloat16* __restrict__ alo, int nquads) {
    int g = blockIdx.x * blockDim.x + threadIdx.x;
    if (g >= nquads) return;
    float4 v4 = reinterpret_cast<const float4*>(x)[g];
    float v[4] = {v4.x, v4.y, v4.z, v4.w};
    uint32_t h0 = pack_bf2(v[0], v[1]), h1 = pack_bf2(v[2], v[3]);
    float f0 = __bfloat162float(__float2bfloat16_rn(v[0]));
    float f1 = __bfloat162float(__float2bfloat16_rn(v[1]));
    float f2 = __bfloat162float(__float2bfloat16_rn(v[2]));
    float f3 = __bfloat162float(__float2bfloat16_rn(v[3]));
    uint32_t l0 = pack_bf2(v[0] - f0, v[1] - f1), l1 = pack_bf2(v[2] - f2, v[3] - f3);
    reinterpret_cast<uint2*>(ahi)[g] = make_uint2(h0, h1);
    reinterpret_cast<uint2*>(alo)[g] = make_uint2(l0, l1);
}

// ---------------- kernel 3: sparse GEMM  CT[N, M] = W(2:4) * XT, transposed store ----------------
// CTA: 128 features x 128 tokens, k64 chunks, 2-stage cp.async, occ 2.
// Warp layout (as R8, known good): 4 feature-warps x 2 token-warps; warp tile 32 feat x 64 tok.
// Fragment loads via ldmatrix.x4 (only change vs R8).
// stage: A(wc) 16K @0, Bhi 16K @16384, Blo 16K @32768, meta 1K @49152
#define ST_A   0
#define ST_BH  16384
#define ST_BL  32768
#define ST_ME  49152
#define ST_SZ  50176
#define SMEM_TOTAL (2 * ST_SZ)   // 100352
#define EPI_STRIDE 36            // floats per token row (144B: 16B-aligned for lds128)

__global__ __launch_bounds__(256, 2)
void gemm_sp(const __nv_bfloat16* __restrict__ Wc, const uint32_t* __restrict__ Meta,
             const __nv_bfloat16* __restrict__ Xhi, const __nv_bfloat16* __restrict__ Xlo,
             const float* __restrict__ bias, float* __restrict__ C, int M) {
    extern __shared__ char smem[];
    const uint32_t sbase = smem_u32(smem);
    const int tid = threadIdx.x;
    const int wid = tid >> 5, lane = tid & 31;
    const int g = lane >> 2, t4 = lane & 3;
    const int kh = lane & 1;           // meta k-half this thread supplies
    const int i_m = lane >> 3;         // ldmatrix matrix index 0..3
    const int j_m = lane & 7;          // ldmatrix row within matrix
    const int wr = wid & 3;            // feature warp: 32 features
    const int wt = wid >> 2;           // token warp: 64 tokens
    const int bn = blockIdx.x * 128;   // feature tile
    const int bt = blockIdx.y * 128;   // token tile

    auto ld_stage = [&](int t, int s) {
        const uint32_t stg = sbase + s * ST_SZ;
#pragma unroll
        for (int j = 0; j < 4; j++) {
            int i = tid + 256 * j;          // 0..1023
            int r = i >> 3, c = i & 7;
            uint32_t sw = (uint32_t)(r * 128 + (((c) ^ (r & 7)) << 4));
            cpasync16(stg + ST_A + sw, Wc + ((size_t)(bn + r) * NCHUNK + t) * 64 + c * 8);
            int tok = bt + r; if (tok > M - 1) tok = M - 1;
            const size_t go = (size_t)tok * K_DIM + t * 64 + c * 8;
            cpasync16(stg + ST_BH + sw, Xhi + go);
            cpasync16(stg + ST_BL + sw, Xlo + go);
        }
        if (tid < 128)
            cpasync8(stg + ST_ME + tid * 8, Meta + (size_t)(bn + tid) * 24 + t * 2);
        CP_COMMIT();
    };

    float acc[2][8][4];
#pragma unroll
    for (int mt = 0; mt < 2; mt++)
#pragma unroll
        for (int nt = 0; nt < 8; nt++)
#pragma unroll
            for (int q = 0; q < 4; q++) acc[mt][nt][q] = 0.0f;

    ld_stage(0, 0);
    ld_stage(1, 1);

    for (int t = 0; t < NCHUNK; t++) {
        if (t == NCHUNK - 1) asm volatile("cp.async.wait_group 0;" ::: "memory");
        else                 asm volatile("cp.async.wait_group 1;" ::: "memory");
        __syncthreads();

        const uint32_t stg = sbase + (t & 1) * ST_SZ;
#pragma unroll
        for (int h = 0; h < 2; h++) {                 // two k32 steps per chunk
            uint32_t e[2], ah[2][4], al[2][4];
#pragma unroll
            for (int mt = 0; mt < 2; mt++) {
                const int rbase = wr * 32 + mt * 16;
                // metadata (m16n8k32, sel 0): T_even k0..15 / T_odd k16..31 of rows g, g+8
                const uint32_t m_a = lds32(stg + ST_ME + (rbase + g) * 8 + h * 4);
                const uint32_t m_b = lds32(stg + ST_ME + (rbase + g + 8) * 8 + h * 4);
                e[mt] = ((m_a >> (16 * kh)) & 0xFFFFu) | (((m_b >> (16 * kh)) & 0xFFFFu) << 16);
                // A fragments via ldmatrix.x4:
                //   matrix 0: rows 0-7,  k' octet h*16+0..7   -> ah[mt][0]
                //   matrix 1: rows 8-15, k' octet h*16+0..7   -> ah[mt][1]
                //   matrix 2: rows 0-7,  k' octet h*16+8..15  -> ah[mt][2]
                //   matrix 3: rows 8-15, k' octet h*16+8..15  -> ah[mt][3]
                const int arow = rbase + ((i_m & 1) << 3) + j_m;
                const uint32_t abase = stg + ST_A + arow * 128;
                const int sh = h * 2 + (i_m >> 1);
                ldsm4(ah[mt], abase + (((sh    ) ^ (arow & 7)) << 4));
                ldsm4(al[mt], abase + (((sh + 4) ^ (arow & 7)) << 4));
            }
#pragma unroll
            for (int nt = 0; nt < 8; nt++) {
                // B fragments via ldmatrix.x4: matrix i = k-octet (4h+i) of 8 token rows
                const int tok = wt * 64 + nt * 8 + j_m;
                const uint32_t sw = (uint32_t)(((4 * h + i_m) ^ (tok & 7)) << 4);
                const uint32_t bb = tok * 128 + sw;
                uint32_t bh[4], bl[4];
                ldsm4(bh, stg + ST_BH + bb);
                ldsm4(bl, stg + ST_BL + bb);
#pragma unroll
                for (int mt = 0; mt < 2; mt++) {
                    mma_sp_bf16(acc[mt][nt], ah[mt], bh, e[mt]);   // hi*hi
                    mma_sp_bf16(acc[mt][nt], ah[mt], bl, e[mt]);   // hi*lo
                    mma_sp_bf16(acc[mt][nt], al[mt], bh, e[mt]);   // lo*hi
                }
            }
        }
        __syncthreads();
        if (t + 2 < NCHUNK) ld_stage(t + 2, t & 1);
    }

    // ---- epilogue: bias + smem transpose (CT frag -> C[token][feature]) ----  (R8 verbatim)
    __syncthreads();   // done reading stages; reuse smem
    float bias_v[2][2];
#pragma unroll
    for (int mt = 0; mt < 2; mt++) {
        const int f = bn + wr * 32 + mt * 16 + g;
        bias_v[mt][0] = __ldg(bias + f);
        bias_v[mt][1] = __ldg(bias + f + 8);
    }
    // warp-private region: 64 tokens x EPI_STRIDE floats (144B rows: aligned + near-conflict-free)
    const uint32_t wb = sbase + wid * (64 * EPI_STRIDE * 4);
#pragma unroll
    for (int mt = 0; mt < 2; mt++)
#pragma unroll
        for (int nt = 0; nt < 8; nt++) {
            const int tokL = nt * 8 + 2 * t4;
            const int fL = mt * 16 + g;
            const uint32_t a0 = wb + (uint32_t)(tokL * EPI_STRIDE + fL) * 4;
            sts32(a0,                        acc[mt][nt][0] + bias_v[mt][0]);
            sts32(a0 + EPI_STRIDE * 4,       acc[mt][nt][1] + bias_v[mt][0]);  // token+1
            sts32(a0 + 32,                   acc[mt][nt][2] + bias_v[mt][1]);  // feat+8
            sts32(a0 + EPI_STRIDE * 4 + 32,  acc[mt][nt][3] + bias_v[mt][1]);
        }
    __syncwarp();
#pragma unroll
    for (int it = 0; it < 8; it++) {
        const int tokL = it * 8 + g;
        const int tokG = bt + wt * 64 + tokL;
        if (tokG < M) {
#pragma unroll
            for (int j = 0; j < 2; j++) {
                const int fl = t4 * 4 + j * 16;
                float4 v = lds128(wb + (uint32_t)(tokL * EPI_STRIDE + fl) * 4);
                *reinterpret_cast<float4*>(C + (size_t)tokG * N_DIM + bn + wr * 32 + fl) = v;
            }
        }
    }
}

// ---------------------------------------------------------------------------
extern "C" void kernel_launch(void* const* d_in, const int* in_sizes, int n_in,
                              void* d_out, int out_size) {
    const float* x    = (const float*)d_in[0];  // [M, 768]
    const float* w    = (const float*)d_in[1];  // [3072, 768]
    const float* bias = (const float*)d_in[2];  // [3072]
    float* out        = (float*)d_out;          // [M, 3072]
    (void)n_in; (void)out_size;

    const int M = in_sizes[0] / K_DIM;          // 12608

    __nv_bfloat16 *ahi, *alo, *wc;
    uint32_t* meta;
    cudaGetSymbolAddress((void**)&ahi, g_a_hi);
    cudaGetSymbolAddress((void**)&alo, g_a_lo);
    cudaGetSymbolAddress((void**)&wc, g_wc);
    cudaGetSymbolAddress((void**)&meta, g_meta);

    const int totalW = N_DIM * 24;              // (row, k32 block)
    mask_compress_w<<<(totalW + 255) / 256, 256>>>(w, wc, meta, totalW);
    const int nquads = (M * K_DIM) / 4;
    split_x<<<(nquads + 255) / 256, 256>>>(x, ahi, alo, nquads);

    cudaFuncSetAttribute(gemm_sp, cudaFuncAttributeMaxDynamicSharedMemorySize, SMEM_TOTAL);
    dim3 grid(N_DIM / 128, (M + 127) / 128);    // (24, 99)
    gemm_sp<<<grid, 256, SMEM_TOTAL>>>(wc, meta, ahi, alo, bias, out, M);
}